// round 15
// baseline (speedup 1.0000x reference)
#include <cuda_runtime.h>
#include <stdint.h>

#define D     10000
#define F     5001      // Hermitian bins 0..5000
#define NB    64
#define NS    128
#define NA    10
#define NR    8
#define NP    256
#define FFTTHREADS 1024
#define BG    8         // batches per combine block
#define SHALF 64        // tokens per combine z-slice
#define NZ    2

// proj tiling (tensor-core, pre-split hi/lo) -- R12 known-good
#define PSPLIT 125
#define PLEN   80       // D / PSPLIT, divisible by 8
#define PSTRIDE 84      // row stride (words): 21g+t4 mod 32 hits all banks
#define PROJ_SMEM (4 * 64 * PSTRIDE * 4)   // 86016 B -> 2 CTAs/SM

// FFT skew: pad 3 float2 per decade (stage-0 store stride 13)
__device__ __forceinline__ int SKF(int i) { return i + 3 * (i / 10); }
#define SBUF  13000

// ---------------- device scratch ----------------
__device__ float2 Fa_g[NA * F];
__device__ float2 Fp_g[NS * F];
__device__ float2 Fc_g[F];
__device__ float2 Freq_g[NZ][NB * F];          // partial accumulators
__device__ float  Mol_g[NB * D];

__device__ __forceinline__ float2 cmulf(float2 a, float2 b) {
    return make_float2(a.x * b.x - a.y * b.y, a.x * b.y + a.y * b.x);
}

// DFT-5 constants: W5 = e^{-2pi i/5}
#define C51  0.30901699437494742f
#define S51  0.95105651629515357f
#define C52 (-0.80901699437494745f)
#define S52  0.58778525229247314f
// W10^t = (CT_t, -ST_t)
#define CT1  0.80901699437494742f
#define ST1  0.58778525229247314f
#define CT2  0.30901699437494742f
#define ST2  0.95105651629515357f

// ---------------- DFT-5 (Winograd-style, immediate constants) ----------
__device__ __forceinline__ void dft5(const float2* a, float2* A) {
    float2 t1 = make_float2(a[1].x + a[4].x, a[1].y + a[4].y);
    float2 t2 = make_float2(a[2].x + a[3].x, a[2].y + a[3].y);
    float2 t3 = make_float2(a[1].x - a[4].x, a[1].y - a[4].y);
    float2 t4 = make_float2(a[2].x - a[3].x, a[2].y - a[3].y);
    A[0] = make_float2(a[0].x + t1.x + t2.x, a[0].y + t1.y + t2.y);
    float2 b1 = make_float2(a[0].x + C51 * t1.x + C52 * t2.x,
                            a[0].y + C51 * t1.y + C52 * t2.y);
    float2 b2 = make_float2(a[0].x + C52 * t1.x + C51 * t2.x,
                            a[0].y + C52 * t1.y + C51 * t2.y);
    float2 p  = make_float2(S51 * t3.x + S52 * t4.x, S51 * t3.y + S52 * t4.y);
    float2 q  = make_float2(S52 * t3.x - S51 * t4.x, S52 * t3.y - S51 * t4.y);
    A[1] = make_float2(b1.x + p.y, b1.y - p.x);
    A[4] = make_float2(b1.x - p.y, b1.y + p.x);
    A[2] = make_float2(b2.x + q.y, b2.y - q.x);
    A[3] = make_float2(b2.x - q.y, b2.y + q.x);
}

// ---------------- DFT-10 = 2 x DFT-5 + radix-2 combine ----------------
__device__ __forceinline__ void dft10(const float2* u, float2* v) {
    float2 E[5], O[5];
    {
        float2 a[5];
#pragma unroll
        for (int r = 0; r < 5; r++) a[r] = u[2 * r];
        dft5(a, E);
#pragma unroll
        for (int r = 0; r < 5; r++) a[r] = u[2 * r + 1];
        dft5(a, O);
    }
    float2 wo;
    v[0] = make_float2(E[0].x + O[0].x, E[0].y + O[0].y);
    v[5] = make_float2(E[0].x - O[0].x, E[0].y - O[0].y);
    wo = cmulf(O[1], make_float2(CT1, -ST1));
    v[1] = make_float2(E[1].x + wo.x, E[1].y + wo.y);
    v[6] = make_float2(E[1].x - wo.x, E[1].y - wo.y);
    wo = cmulf(O[2], make_float2(CT2, -ST2));
    v[2] = make_float2(E[2].x + wo.x, E[2].y + wo.y);
    v[7] = make_float2(E[2].x - wo.x, E[2].y - wo.y);
    wo = cmulf(O[3], make_float2(-CT2, -ST2));
    v[3] = make_float2(E[3].x + wo.x, E[3].y + wo.y);
    v[8] = make_float2(E[3].x - wo.x, E[3].y - wo.y);
    wo = cmulf(O[4], make_float2(-CT1, -ST1));
    v[4] = make_float2(E[4].x + wo.x, E[4].y + wo.y);
    v[9] = make_float2(E[4].x - wo.x, E[4].y - wo.y);
}

// ---------------- on-the-fly stage twiddles: W^(row*t), t=1..9 ----------
__device__ __forceinline__ void twiddle9_otf(float2* v, int row) {
    float s, c;
    sincospif((float)row * (-1.0f / 5000.0f), &s, &c);
    float2 w1 = make_float2(c, s);
    float2 w2 = cmulf(w1, w1);
    float2 w3 = cmulf(w2, w1);
    float2 w4 = cmulf(w2, w2);
    float2 w5 = cmulf(w4, w1);
    float2 w6 = cmulf(w4, w2);
    float2 w7 = cmulf(w4, w3);
    float2 w8 = cmulf(w4, w4);
    float2 w9 = cmulf(w8, w1);
    v[1] = cmulf(v[1], w1);
    v[2] = cmulf(v[2], w2);
    v[3] = cmulf(v[3], w3);
    v[4] = cmulf(v[4], w4);
    v[5] = cmulf(v[5], w5);
    v[6] = cmulf(v[6], w6);
    v[7] = cmulf(v[7], w7);
    v[8] = cmulf(v[8], w8);
    v[9] = cmulf(v[9], w9);
}

// ---------------- middle stages 1 & 2 (smem -> smem) ----------------
__device__ __forceinline__ void fft_mid(float2* bufA, float2* bufB, int bf) {
    if (bf < 1000) {
        int j = bf / 10, k = bf - j * 10;
        float2 u[10];
#pragma unroll
        for (int q = 0; q < 10; q++) u[q] = bufA[SKF(bf + q * 1000)];
        float2 v[10];
        dft10(u, v);
        if (j) twiddle9_otf(v, j * 10);
        int ob = k + 100 * j;
#pragma unroll
        for (int t = 0; t < 10; t++) bufB[SKF(ob + 10 * t)] = v[t];
    }
    __syncthreads();
    if (bf < 1000) {
        int j = bf / 100, k = bf - j * 100;
        float2 u[10];
#pragma unroll
        for (int q = 0; q < 10; q++) u[q] = bufB[SKF(bf + q * 1000)];
        float2 v[10];
        dft10(u, v);
        if (j) twiddle9_otf(v, j * 100);
        int ob = k + 1000 * j;
#pragma unroll
        for (int t = 0; t < 10; t++) bufA[SKF(ob + 100 * t)] = v[t];
    }
    __syncthreads();
}

// ---------------- forward FFT (+ bias-init in extra block) -------------
__global__ void __launch_bounds__(FFTTHREADS, 1)
fwd_fft_kernel(const float* __restrict__ atom,
               const float* __restrict__ pos,
               const float* __restrict__ clos,
               const float* __restrict__ bias,
               float* __restrict__ out) {
    // allow next kernel (combine) to prelaunch its prologue
    cudaTriggerProgrammaticLaunchCompletion();
    int vb = blockIdx.x;
    if (vb == NA + NS + 1) {   // init out = bias (must precede proj atomics)
        for (int i = threadIdx.x; i < NB * NP; i += blockDim.x)
            out[i] = bias[i & (NP - 1)];
        return;
    }
    extern __shared__ float2 sb[];
    float2* bufA = sb;
    float2* bufB = sb + SBUF;
    const float* x;
    float2* outF;
    if (vb < NA)           { x = atom + vb * D;        outF = Fa_g + vb * F; }
    else if (vb < NA + NS) { x = pos + (vb - NA) * D;  outF = Fp_g + (vb - NA) * F; }
    else                   { x = clos;                 outF = Fc_g; }

    int bf = threadIdx.x;
    if (bf < 1000) {
        float2 u[10];
#pragma unroll
        for (int q = 0; q < 10; q++) u[q] = make_float2(x[bf + q * 1000], 0.f);
        float2 v[10];
        dft10(u, v);
        if (bf) twiddle9_otf(v, bf);
#pragma unroll
        for (int t = 0; t < 10; t++) bufA[13 * bf + t] = v[t];
    }
    __syncthreads();

    fft_mid(bufA, bufB, bf);

    if (bf < 1000) {
        float2 u[10];
#pragma unroll
        for (int q = 0; q < 10; q++) u[q] = bufA[SKF(bf + q * 1000)];
        float2 v[10];
        dft10(u, v);
#pragma unroll
        for (int t = 0; t < 10; t++) {
            int p = bf + 1000 * t;
            if (p < F) outF[p] = v[t];
        }
    }
}

// ---------------- frequency combine: 2-way z-split over s --------------
// PDL: mask/index prologue runs before waiting on fwd.
__global__ void combine_kernel(const float* __restrict__ tmask,
                               const float* __restrict__ rmask,
                               const int*   __restrict__ aidx,
                               const int*   __restrict__ rpos) {
    cudaTriggerProgrammaticLaunchCompletion();
    __shared__ float2 s_mi[BG][SHALF];
    __shared__ int   s_rp[BG][NR][2];
    __shared__ float s_rm[BG][NR];
    __shared__ float2 s_fa[NA][128];

    int b0 = blockIdx.y * BG;
    int z  = blockIdx.z;
    int s0 = z * SHALF;
    int tx = threadIdx.x;

    // ---- independent prologue (inputs only) ----
    for (int t = tx; t < BG * SHALF; t += 128) {
        int bb = t / SHALF, s = t % SHALF;
        s_mi[bb][s] = make_float2(tmask[(b0 + bb) * NS + s0 + s],
                                  __int_as_float(aidx[(b0 + bb) * NS + s0 + s]));
    }
    if (z == 1) {
        for (int t = tx; t < BG * NR; t += 128) {
            int bb = t / NR, r = t % NR;
            s_rp[bb][r][0] = rpos[((b0 + bb) * NR + r) * 2 + 0];
            s_rp[bb][r][1] = rpos[((b0 + bb) * NR + r) * 2 + 1];
            s_rm[bb][r]    = rmask[(b0 + bb) * NR + r];
        }
    }

    // ---- wait for fwd_fft to complete ----
    cudaGridDependencySynchronize();

    int f = blockIdx.x * 128 + tx;
    if (f < F) {
        for (int i = 0; i < NA; i++) s_fa[i][tx] = Fa_g[i * F + f];
    }
    __syncthreads();
    if (f >= F) return;

    float2 acc[BG];
#pragma unroll
    for (int bb = 0; bb < BG; bb++) acc[bb] = make_float2(0.f, 0.f);

#pragma unroll 4
    for (int s = 0; s < SHALF; s++) {
        float2 fp = Fp_g[(s0 + s) * F + f];
        float nfpy = -fp.y;
#pragma unroll
        for (int bb = 0; bb < BG; bb++) {
            float2 mi = s_mi[bb][s];
            int    a  = __float_as_int(mi.y);
            float2 fa = s_fa[a][tx];
            float p = mi.x * fa.x;
            float q = mi.x * fa.y;
            acc[bb].x += p * fp.x;
            acc[bb].x += q * nfpy;
            acc[bb].y += p * fp.y;
            acc[bb].y += q * fp.x;
        }
    }
    if (z == 1) {
        float2 fc = Fc_g[f];
#pragma unroll
        for (int bb = 0; bb < BG; bb++) {
            for (int r = 0; r < NR; r++) {
                float2 f0 = Fp_g[s_rp[bb][r][0] * F + f];
                float2 f1 = Fp_g[s_rp[bb][r][1] * F + f];
                float2 t  = cmulf(cmulf(f0, f1), fc);
                float mm  = s_rm[bb][r];
                acc[bb].x += mm * t.x;
                acc[bb].y += mm * t.y;
            }
        }
    }
#pragma unroll
    for (int bb = 0; bb < BG; bb++)
        Freq_g[z][(b0 + bb) * F + f] = acc[bb];
}

// ---------------- inverse FFT (sum partials, Hermitian, conj) ----------
__global__ void __launch_bounds__(FFTTHREADS, 1)
inv_fft_kernel() {
    cudaTriggerProgrammaticLaunchCompletion();
    extern __shared__ float2 sb[];
    float2* bufA = sb;
    float2* bufB = sb + SBUF;
    int b = blockIdx.x;
    const float2* in0 = Freq_g[0] + b * F;
    const float2* in1 = Freq_g[1] + b * F;

    // wait for combine
    cudaGridDependencySynchronize();

    int bf = threadIdx.x;
    if (bf < 1000) {
        float2 u[10];
#pragma unroll
        for (int q = 0; q < 10; q++) {
            int i = bf + q * 1000;
            int ii = (i < F) ? i : (D - i);
            float2 za = in0[ii];
            float2 zb = in1[ii];
            float2 z = make_float2(za.x + zb.x, za.y + zb.y);
            if (i < F) z.y = -z.y;     // conj for lower half
            u[q] = z;
        }
        float2 v[10];
        dft10(u, v);
        if (bf) twiddle9_otf(v, bf);
#pragma unroll
        for (int t = 0; t < 10; t++) bufA[13 * bf + t] = v[t];
    }
    __syncthreads();

    fft_mid(bufA, bufB, bf);

    if (bf < 1000) {
        float2 u[10];
#pragma unroll
        for (int q = 0; q < 10; q++) u[q] = bufA[SKF(bf + q * 1000)];
        float2 v[10];
        dft10(u, v);
        const float inv = 1.0f / (float)D;
        float* mo = Mol_g + b * D;
#pragma unroll
        for (int t = 0; t < 10; t++) mo[bf + 1000 * t] = v[t].x * inv;
    }
}

// ---------------- 3xTF32 helpers ----------------
__device__ __forceinline__ void tf32_split(float x, uint32_t& hi, uint32_t& lo) {
    asm("cvt.rna.tf32.f32 %0, %1;" : "=r"(hi) : "f"(x));
    float r = x - __uint_as_float(hi);
    asm("cvt.rna.tf32.f32 %0, %1;" : "=r"(lo) : "f"(r));
}

__device__ __forceinline__ void mma_tf32(float* c, const uint32_t* a,
                                         uint32_t b0, uint32_t b1) {
    asm volatile(
        "mma.sync.aligned.m16n8k8.row.col.f32.tf32.tf32.f32 "
        "{%0,%1,%2,%3}, {%4,%5,%6,%7}, {%8,%9}, {%0,%1,%2,%3};"
        : "+f"(c[0]), "+f"(c[1]), "+f"(c[2]), "+f"(c[3])
        : "r"(a[0]), "r"(a[1]), "r"(a[2]), "r"(a[3]), "r"(b0), "r"(b1));
}

// ---------------- projection: 3xTF32, pre-split tiles, split-k ---------
// R12 known-good + PDL: W tile loaded/split BEFORE waiting on inv.
// grid (NP/64 = 4, PSPLIT = 125), block 256 (8 warps), 2 CTAs/SM.
__global__ void __launch_bounds__(256)
proj_kernel(const float* __restrict__ Wm, float* __restrict__ out) {
    extern __shared__ uint32_t ps[];
    uint32_t* sAhi = ps;                          // [64][PSTRIDE]
    uint32_t* sAlo = ps + 64 * PSTRIDE;
    uint32_t* sWhi = ps + 2 * 64 * PSTRIDE;
    uint32_t* sWlo = ps + 3 * 64 * PSTRIDE;
    int pb = blockIdx.x;
    int ds = blockIdx.y;
    int dbase = ds * PLEN;
    int tid = threadIdx.x;

    // ---- independent prologue: load + split W tile (input only) ----
#pragma unroll
    for (int j = 0; j < 5; j++) {
        int v = tid + j * 256;
        int r = v / 20, cq = v - r * 20;
        float4 x = *reinterpret_cast<const float4*>(&Wm[(pb * 64 + r) * D + dbase + cq * 4]);
        uint4 h, l;
        tf32_split(x.x, h.x, l.x);
        tf32_split(x.y, h.y, l.y);
        tf32_split(x.z, h.z, l.z);
        tf32_split(x.w, h.w, l.w);
        *reinterpret_cast<uint4*>(&sWhi[r * PSTRIDE + cq * 4]) = h;
        *reinterpret_cast<uint4*>(&sWlo[r * PSTRIDE + cq * 4]) = l;
    }

    // ---- wait for inv_fft, then load Mol tile ----
    cudaGridDependencySynchronize();

#pragma unroll
    for (int j = 0; j < 5; j++) {
        int v = tid + j * 256;                 // v < 1280
        int r = v / 20, cq = v - r * 20;
        float4 x = *reinterpret_cast<const float4*>(&Mol_g[r * D + dbase + cq * 4]);
        uint4 h, l;
        tf32_split(x.x, h.x, l.x);
        tf32_split(x.y, h.y, l.y);
        tf32_split(x.z, h.z, l.z);
        tf32_split(x.w, h.w, l.w);
        *reinterpret_cast<uint4*>(&sAhi[r * PSTRIDE + cq * 4]) = h;
        *reinterpret_cast<uint4*>(&sAlo[r * PSTRIDE + cq * 4]) = l;
    }
    __syncthreads();

    int wid  = tid >> 5;
    int lane = tid & 31;
    int g  = lane >> 2;        // group id 0..7
    int t4 = lane & 3;         // thread-in-group 0..3
    int mi = wid & 3;          // m-tile (16 b rows)
    int nh = wid >> 2;         // n-half (32 p cols)

    int arow = mi * 16 + g;
    int a0 = arow * PSTRIDE + t4;
    int a1 = (arow + 8) * PSTRIDE + t4;
    float acc[4][4];
#pragma unroll
    for (int i = 0; i < 4; i++)
#pragma unroll
        for (int j = 0; j < 4; j++) acc[i][j] = 0.f;

#pragma unroll
    for (int ks = 0; ks < PLEN / 8; ks++) {
        int k0 = ks * 8;
        uint32_t ah[4], al[4];
        ah[0] = sAhi[a0 + k0];     al[0] = sAlo[a0 + k0];
        ah[1] = sAhi[a1 + k0];     al[1] = sAlo[a1 + k0];
        ah[2] = sAhi[a0 + k0 + 4]; al[2] = sAlo[a0 + k0 + 4];
        ah[3] = sAhi[a1 + k0 + 4]; al[3] = sAlo[a1 + k0 + 4];
#pragma unroll
        for (int nt = 0; nt < 4; nt++) {
            int nrow = (nh * 32 + nt * 8 + g) * PSTRIDE + t4;
            uint32_t bh0 = sWhi[nrow + k0];
            uint32_t bh1 = sWhi[nrow + k0 + 4];
            uint32_t bl0 = sWlo[nrow + k0];
            uint32_t bl1 = sWlo[nrow + k0 + 4];
            mma_tf32(acc[nt], ah, bh0, bh1);   // hi*hi
            mma_tf32(acc[nt], ah, bl0, bl1);   // hi*lo
            mma_tf32(acc[nt], al, bh0, bh1);   // lo*hi
        }
    }

    // epilogue: atomic add into bias-initialized out
#pragma unroll
    for (int nt = 0; nt < 4; nt++) {
        int pcol = pb * 64 + nh * 32 + nt * 8 + t4 * 2;
        int brow = mi * 16 + g;
        atomicAdd(&out[brow * NP + pcol],           acc[nt][0]);
        atomicAdd(&out[brow * NP + pcol + 1],       acc[nt][1]);
        atomicAdd(&out[(brow + 8) * NP + pcol],     acc[nt][2]);
        atomicAdd(&out[(brow + 8) * NP + pcol + 1], acc[nt][3]);
    }
}

// ---------------- launch ----------------
extern "C" void kernel_launch(void* const* d_in, const int* in_sizes, int n_in,
                              void* d_out, int out_size) {
    const float* atom  = (const float*)d_in[0];
    const float* pos   = (const float*)d_in[1];
    const float* clos  = (const float*)d_in[2];
    const float* Wm    = (const float*)d_in[3];
    const float* bias  = (const float*)d_in[4];
    const float* tmask = (const float*)d_in[5];
    const float* rmask = (const float*)d_in[6];
    const int*   aidx  = (const int*)d_in[7];
    const int*   rpos  = (const int*)d_in[8];
    float* out = (float*)d_out;

    size_t smem = 2 * (size_t)SBUF * sizeof(float2);   // 208000 B
    cudaFuncSetAttribute(fwd_fft_kernel,
                         cudaFuncAttributeMaxDynamicSharedMemorySize, (int)smem);
    cudaFuncSetAttribute(inv_fft_kernel,
                         cudaFuncAttributeMaxDynamicSharedMemorySize, (int)smem);
    cudaFuncSetAttribute(proj_kernel,
                         cudaFuncAttributeMaxDynamicSharedMemorySize, PROJ_SMEM);

    // kernel 1: forward FFT (normal launch)
    fwd_fft_kernel<<<NA + NS + 2, FFTTHREADS, smem>>>(atom, pos, clos, bias, out);

    // PDL attribute shared by the dependent launches
    cudaLaunchAttribute pdl[1];
    pdl[0].id = cudaLaunchAttributeProgrammaticStreamSerialization;
    pdl[0].val.programmaticStreamSerializationAllowed = 1;

    // kernel 2: combine (PDL — prologue overlaps fwd tail)
    {
        cudaLaunchConfig_t cfg = {};
        cfg.gridDim  = dim3((F + 127) / 128, NB / BG, NZ);
        cfg.blockDim = dim3(128, 1, 1);
        cfg.dynamicSmemBytes = 0;
        cfg.attrs = pdl;
        cfg.numAttrs = 1;
        cudaLaunchKernelEx(&cfg, combine_kernel, tmask, rmask, aidx, rpos);
    }

    // kernel 3: inverse FFT (PDL)
    {
        cudaLaunchConfig_t cfg = {};
        cfg.gridDim  = dim3(NB, 1, 1);
        cfg.blockDim = dim3(FFTTHREADS, 1, 1);
        cfg.dynamicSmemBytes = smem;
        cfg.attrs = pdl;
        cfg.numAttrs = 1;
        cudaLaunchKernelEx(&cfg, inv_fft_kernel);
    }

    // kernel 4: projection (PDL — W-tile load/split overlaps inv)
    {
        cudaLaunchConfig_t cfg = {};
        cfg.gridDim  = dim3(NP / 64, PSPLIT, 1);
        cfg.blockDim = dim3(256, 1, 1);
        cfg.dynamicSmemBytes = PROJ_SMEM;
        cfg.attrs = pdl;
        cfg.numAttrs = 1;
        cudaLaunchKernelEx(&cfg, proj_kernel, Wm, out);
    }
}

// round 16
// speedup vs baseline: 1.3204x; 1.3204x over previous
#include <cuda_runtime.h>
#include <stdint.h>

#define D     10000
#define F     5001      // Hermitian bins 0..5000
#define NB    64
#define NS    128
#define NA    10
#define NR    8
#define NP    256
#define FFTTHREADS 1024
#define BG    8         // batches per combine block
#define SHALF 64        // tokens per combine z-slice
#define NZ    2

// proj tiling (tensor-core, pre-split hi/lo) -- R12 known-good
#define PSPLIT 125
#define PLEN   80       // D / PSPLIT, divisible by 8
#define PSTRIDE 84      // row stride (words): 21g+t4 mod 32 hits all banks
#define PROJ_SMEM (4 * 64 * PSTRIDE * 4)   // 86016 B -> 2 CTAs/SM

// FFT skew: pad 3 float2 per decade (stage-0 store stride 13)
__device__ __forceinline__ int SKF(int i) { return i + 3 * (i / 10); }
#define SBUF  13000
// FFT smem: ping-pong (2*SBUF) + twiddle base table (1000)
#define FFT_SMEM ((2 * SBUF + 1000) * 8)   // 216000 B

// ---------------- device scratch ----------------
__device__ float2 Fa_g[NA * F];
__device__ float2 Fp_g[NS * F];
__device__ float2 Fc_g[F];
__device__ float2 Freq_g[NZ][NB * F];          // partial accumulators
__device__ float  Mol_g[NB * D];

__device__ __forceinline__ float2 cmulf(float2 a, float2 b) {
    return make_float2(a.x * b.x - a.y * b.y, a.x * b.y + a.y * b.x);
}

// DFT-5 constants: W5 = e^{-2pi i/5}
#define C51  0.30901699437494742f
#define S51  0.95105651629515357f
#define C52 (-0.80901699437494745f)
#define S52  0.58778525229247314f
// W10^t = (CT_t, -ST_t)
#define CT1  0.80901699437494742f
#define ST1  0.58778525229247314f
#define CT2  0.30901699437494742f
#define ST2  0.95105651629515357f

// ---------------- DFT-5 (Winograd-style, immediate constants) ----------
__device__ __forceinline__ void dft5(const float2* a, float2* A) {
    float2 t1 = make_float2(a[1].x + a[4].x, a[1].y + a[4].y);
    float2 t2 = make_float2(a[2].x + a[3].x, a[2].y + a[3].y);
    float2 t3 = make_float2(a[1].x - a[4].x, a[1].y - a[4].y);
    float2 t4 = make_float2(a[2].x - a[3].x, a[2].y - a[3].y);
    A[0] = make_float2(a[0].x + t1.x + t2.x, a[0].y + t1.y + t2.y);
    float2 b1 = make_float2(a[0].x + C51 * t1.x + C52 * t2.x,
                            a[0].y + C51 * t1.y + C52 * t2.y);
    float2 b2 = make_float2(a[0].x + C52 * t1.x + C51 * t2.x,
                            a[0].y + C52 * t1.y + C51 * t2.y);
    float2 p  = make_float2(S51 * t3.x + S52 * t4.x, S51 * t3.y + S52 * t4.y);
    float2 q  = make_float2(S52 * t3.x - S51 * t4.x, S52 * t3.y - S51 * t4.y);
    A[1] = make_float2(b1.x + p.y, b1.y - p.x);
    A[4] = make_float2(b1.x - p.y, b1.y + p.x);
    A[2] = make_float2(b2.x + q.y, b2.y - q.x);
    A[3] = make_float2(b2.x - q.y, b2.y + q.x);
}

// ---------------- DFT-10 = 2 x DFT-5 + radix-2 combine ----------------
__device__ __forceinline__ void dft10(const float2* u, float2* v) {
    float2 E[5], O[5];
    {
        float2 a[5];
#pragma unroll
        for (int r = 0; r < 5; r++) a[r] = u[2 * r];
        dft5(a, E);
#pragma unroll
        for (int r = 0; r < 5; r++) a[r] = u[2 * r + 1];
        dft5(a, O);
    }
    float2 wo;
    v[0] = make_float2(E[0].x + O[0].x, E[0].y + O[0].y);
    v[5] = make_float2(E[0].x - O[0].x, E[0].y - O[0].y);
    wo = cmulf(O[1], make_float2(CT1, -ST1));
    v[1] = make_float2(E[1].x + wo.x, E[1].y + wo.y);
    v[6] = make_float2(E[1].x - wo.x, E[1].y - wo.y);
    wo = cmulf(O[2], make_float2(CT2, -ST2));
    v[2] = make_float2(E[2].x + wo.x, E[2].y + wo.y);
    v[7] = make_float2(E[2].x - wo.x, E[2].y - wo.y);
    wo = cmulf(O[3], make_float2(-CT2, -ST2));
    v[3] = make_float2(E[3].x + wo.x, E[3].y + wo.y);
    v[8] = make_float2(E[3].x - wo.x, E[3].y - wo.y);
    wo = cmulf(O[4], make_float2(-CT1, -ST1));
    v[4] = make_float2(E[4].x + wo.x, E[4].y + wo.y);
    v[9] = make_float2(E[4].x - wo.x, E[4].y - wo.y);
}

// ---------------- stage twiddles from smem base table -------------------
// w1 = sT[row] (one LDS), then chained squares/products for w2..w9.
__device__ __forceinline__ void twiddle9_tab(float2* v, const float2* sT, int row) {
    float2 w1 = sT[row];
    float2 w2 = cmulf(w1, w1);
    float2 w3 = cmulf(w2, w1);
    float2 w4 = cmulf(w2, w2);
    float2 w5 = cmulf(w4, w1);
    float2 w6 = cmulf(w4, w2);
    float2 w7 = cmulf(w4, w3);
    float2 w8 = cmulf(w4, w4);
    float2 w9 = cmulf(w8, w1);
    v[1] = cmulf(v[1], w1);
    v[2] = cmulf(v[2], w2);
    v[3] = cmulf(v[3], w3);
    v[4] = cmulf(v[4], w4);
    v[5] = cmulf(v[5], w5);
    v[6] = cmulf(v[6], w6);
    v[7] = cmulf(v[7], w7);
    v[8] = cmulf(v[8], w8);
    v[9] = cmulf(v[9], w9);
}

// ---------------- middle stages 1 & 2 (smem -> smem) ----------------
__device__ __forceinline__ void fft_mid(float2* bufA, float2* bufB,
                                        const float2* sT, int bf) {
    if (bf < 1000) {
        int j = bf / 10, k = bf - j * 10;
        float2 u[10];
#pragma unroll
        for (int q = 0; q < 10; q++) u[q] = bufA[SKF(bf + q * 1000)];
        float2 v[10];
        dft10(u, v);
        if (j) twiddle9_tab(v, sT, j * 10);
        int ob = k + 100 * j;
#pragma unroll
        for (int t = 0; t < 10; t++) bufB[SKF(ob + 10 * t)] = v[t];
    }
    __syncthreads();
    if (bf < 1000) {
        int j = bf / 100, k = bf - j * 100;
        float2 u[10];
#pragma unroll
        for (int q = 0; q < 10; q++) u[q] = bufB[SKF(bf + q * 1000)];
        float2 v[10];
        dft10(u, v);
        if (j) twiddle9_tab(v, sT, j * 100);
        int ob = k + 1000 * j;
#pragma unroll
        for (int t = 0; t < 10; t++) bufA[SKF(ob + 100 * t)] = v[t];
    }
    __syncthreads();
}

// ---------------- forward FFT (+ bias-init in extra block) -------------
__global__ void __launch_bounds__(FFTTHREADS, 1)
fwd_fft_kernel(const float* __restrict__ atom,
               const float* __restrict__ pos,
               const float* __restrict__ clos,
               const float* __restrict__ bias,
               float* __restrict__ out) {
    int vb = blockIdx.x;
    if (vb == NA + NS + 1) {   // init out = bias (must precede proj atomics)
        for (int i = threadIdx.x; i < NB * NP; i += blockDim.x)
            out[i] = bias[i & (NP - 1)];
        return;
    }
    extern __shared__ float2 sb[];
    float2* bufA = sb;
    float2* bufB = sb + SBUF;
    float2* sT   = sb + 2 * SBUF;      // W^i, i<1000
    const float* x;
    float2* outF;
    if (vb < NA)           { x = atom + vb * D;        outF = Fa_g + vb * F; }
    else if (vb < NA + NS) { x = pos + (vb - NA) * D;  outF = Fp_g + (vb - NA) * F; }
    else                   { x = clos;                 outF = Fc_g; }

    int bf = threadIdx.x;
    // build twiddle base table: one sincospif per thread
    if (bf < 1000) {
        float s, c;
        sincospif(-(float)bf / 5000.0f, &s, &c);
        sT[bf] = make_float2(c, s);
    }
    __syncthreads();

    if (bf < 1000) {
        float2 u[10];
#pragma unroll
        for (int q = 0; q < 10; q++) u[q] = make_float2(x[bf + q * 1000], 0.f);
        float2 v[10];
        dft10(u, v);
        if (bf) twiddle9_tab(v, sT, bf);
#pragma unroll
        for (int t = 0; t < 10; t++) bufA[13 * bf + t] = v[t];
    }
    __syncthreads();

    fft_mid(bufA, bufB, sT, bf);

    if (bf < 1000) {
        float2 u[10];
#pragma unroll
        for (int q = 0; q < 10; q++) u[q] = bufA[SKF(bf + q * 1000)];
        float2 v[10];
        dft10(u, v);
#pragma unroll
        for (int t = 0; t < 10; t++) {
            int p = bf + 1000 * t;
            if (p < F) outF[p] = v[t];
        }
    }
}

// ---------------- frequency combine: 2-way z-split over s --------------
__global__ void combine_kernel(const float* __restrict__ tmask,
                               const float* __restrict__ rmask,
                               const int*   __restrict__ aidx,
                               const int*   __restrict__ rpos) {
    __shared__ float2 s_mi[BG][SHALF];
    __shared__ int   s_rp[BG][NR][2];
    __shared__ float s_rm[BG][NR];
    __shared__ float2 s_fa[NA][128];

    int b0 = blockIdx.y * BG;
    int z  = blockIdx.z;
    int s0 = z * SHALF;
    int tx = threadIdx.x;

    for (int t = tx; t < BG * SHALF; t += 128) {
        int bb = t / SHALF, s = t % SHALF;
        s_mi[bb][s] = make_float2(tmask[(b0 + bb) * NS + s0 + s],
                                  __int_as_float(aidx[(b0 + bb) * NS + s0 + s]));
    }
    if (z == 1) {
        for (int t = tx; t < BG * NR; t += 128) {
            int bb = t / NR, r = t % NR;
            s_rp[bb][r][0] = rpos[((b0 + bb) * NR + r) * 2 + 0];
            s_rp[bb][r][1] = rpos[((b0 + bb) * NR + r) * 2 + 1];
            s_rm[bb][r]    = rmask[(b0 + bb) * NR + r];
        }
    }
    int f = blockIdx.x * 128 + tx;
    if (f < F) {
        for (int i = 0; i < NA; i++) s_fa[i][tx] = Fa_g[i * F + f];
    }
    __syncthreads();
    if (f >= F) return;

    float2 acc[BG];
#pragma unroll
    for (int bb = 0; bb < BG; bb++) acc[bb] = make_float2(0.f, 0.f);

#pragma unroll 4
    for (int s = 0; s < SHALF; s++) {
        float2 fp = Fp_g[(s0 + s) * F + f];
        float nfpy = -fp.y;
#pragma unroll
        for (int bb = 0; bb < BG; bb++) {
            float2 mi = s_mi[bb][s];
            int    a  = __float_as_int(mi.y);
            float2 fa = s_fa[a][tx];
            float p = mi.x * fa.x;
            float q = mi.x * fa.y;
            acc[bb].x += p * fp.x;
            acc[bb].x += q * nfpy;
            acc[bb].y += p * fp.y;
            acc[bb].y += q * fp.x;
        }
    }
    if (z == 1) {
        float2 fc = Fc_g[f];
#pragma unroll
        for (int bb = 0; bb < BG; bb++) {
            for (int r = 0; r < NR; r++) {
                float2 f0 = Fp_g[s_rp[bb][r][0] * F + f];
                float2 f1 = Fp_g[s_rp[bb][r][1] * F + f];
                float2 t  = cmulf(cmulf(f0, f1), fc);
                float mm  = s_rm[bb][r];
                acc[bb].x += mm * t.x;
                acc[bb].y += mm * t.y;
            }
        }
    }
#pragma unroll
    for (int bb = 0; bb < BG; bb++)
        Freq_g[z][(b0 + bb) * F + f] = acc[bb];
}

// ---------------- inverse FFT (sum partials, Hermitian, conj) ----------
__global__ void __launch_bounds__(FFTTHREADS, 1)
inv_fft_kernel() {
    extern __shared__ float2 sb[];
    float2* bufA = sb;
    float2* bufB = sb + SBUF;
    float2* sT   = sb + 2 * SBUF;
    int b = blockIdx.x;
    const float2* in0 = Freq_g[0] + b * F;
    const float2* in1 = Freq_g[1] + b * F;

    int bf = threadIdx.x;
    if (bf < 1000) {
        float s, c;
        sincospif(-(float)bf / 5000.0f, &s, &c);
        sT[bf] = make_float2(c, s);
    }
    __syncthreads();

    if (bf < 1000) {
        float2 u[10];
#pragma unroll
        for (int q = 0; q < 10; q++) {
            int i = bf + q * 1000;
            int ii = (i < F) ? i : (D - i);
            float2 za = in0[ii];
            float2 zb = in1[ii];
            float2 z = make_float2(za.x + zb.x, za.y + zb.y);
            if (i < F) z.y = -z.y;     // conj for lower half
            u[q] = z;
        }
        float2 v[10];
        dft10(u, v);
        if (bf) twiddle9_tab(v, sT, bf);
#pragma unroll
        for (int t = 0; t < 10; t++) bufA[13 * bf + t] = v[t];
    }
    __syncthreads();

    fft_mid(bufA, bufB, sT, bf);

    if (bf < 1000) {
        float2 u[10];
#pragma unroll
        for (int q = 0; q < 10; q++) u[q] = bufA[SKF(bf + q * 1000)];
        float2 v[10];
        dft10(u, v);
        const float inv = 1.0f / (float)D;
        float* mo = Mol_g + b * D;
#pragma unroll
        for (int t = 0; t < 10; t++) mo[bf + 1000 * t] = v[t].x * inv;
    }
}

// ---------------- 3xTF32 helpers ----------------
__device__ __forceinline__ void tf32_split(float x, uint32_t& hi, uint32_t& lo) {
    asm("cvt.rna.tf32.f32 %0, %1;" : "=r"(hi) : "f"(x));
    float r = x - __uint_as_float(hi);
    asm("cvt.rna.tf32.f32 %0, %1;" : "=r"(lo) : "f"(r));
}

__device__ __forceinline__ void mma_tf32(float* c, const uint32_t* a,
                                         uint32_t b0, uint32_t b1) {
    asm volatile(
        "mma.sync.aligned.m16n8k8.row.col.f32.tf32.tf32.f32 "
        "{%0,%1,%2,%3}, {%4,%5,%6,%7}, {%8,%9}, {%0,%1,%2,%3};"
        : "+f"(c[0]), "+f"(c[1]), "+f"(c[2]), "+f"(c[3])
        : "r"(a[0]), "r"(a[1]), "r"(a[2]), "r"(a[3]), "r"(b0), "r"(b1));
}

// ---------------- projection: 3xTF32, pre-split tiles, split-k ---------
// R12 known-good. grid (NP/64 = 4, PSPLIT = 125), block 256, 2 CTAs/SM.
__global__ void __launch_bounds__(256)
proj_kernel(const float* __restrict__ Wm, float* __restrict__ out) {
    extern __shared__ uint32_t ps[];
    uint32_t* sAhi = ps;                          // [64][PSTRIDE]
    uint32_t* sAlo = ps + 64 * PSTRIDE;
    uint32_t* sWhi = ps + 2 * 64 * PSTRIDE;
    uint32_t* sWlo = ps + 3 * 64 * PSTRIDE;
    int pb = blockIdx.x;
    int ds = blockIdx.y;
    int dbase = ds * PLEN;
    int tid = threadIdx.x;

    // load + split once: 5 float4 per thread per tile
#pragma unroll
    for (int j = 0; j < 5; j++) {
        int v = tid + j * 256;                 // v < 1280
        int r = v / 20, cq = v - r * 20;
        float4 x = *reinterpret_cast<const float4*>(&Mol_g[r * D + dbase + cq * 4]);
        uint4 h, l;
        tf32_split(x.x, h.x, l.x);
        tf32_split(x.y, h.y, l.y);
        tf32_split(x.z, h.z, l.z);
        tf32_split(x.w, h.w, l.w);
        *reinterpret_cast<uint4*>(&sAhi[r * PSTRIDE + cq * 4]) = h;
        *reinterpret_cast<uint4*>(&sAlo[r * PSTRIDE + cq * 4]) = l;
    }
#pragma unroll
    for (int j = 0; j < 5; j++) {
        int v = tid + j * 256;
        int r = v / 20, cq = v - r * 20;
        float4 x = *reinterpret_cast<const float4*>(&Wm[(pb * 64 + r) * D + dbase + cq * 4]);
        uint4 h, l;
        tf32_split(x.x, h.x, l.x);
        tf32_split(x.y, h.y, l.y);
        tf32_split(x.z, h.z, l.z);
        tf32_split(x.w, h.w, l.w);
        *reinterpret_cast<uint4*>(&sWhi[r * PSTRIDE + cq * 4]) = h;
        *reinterpret_cast<uint4*>(&sWlo[r * PSTRIDE + cq * 4]) = l;
    }
    __syncthreads();

    int wid  = tid >> 5;
    int lane = tid & 31;
    int g  = lane >> 2;        // group id 0..7
    int t4 = lane & 3;         // thread-in-group 0..3
    int mi = wid & 3;          // m-tile (16 b rows)
    int nh = wid >> 2;         // n-half (32 p cols)

    int arow = mi * 16 + g;
    int a0 = arow * PSTRIDE + t4;
    int a1 = (arow + 8) * PSTRIDE + t4;
    float acc[4][4];
#pragma unroll
    for (int i = 0; i < 4; i++)
#pragma unroll
        for (int j = 0; j < 4; j++) acc[i][j] = 0.f;

#pragma unroll
    for (int ks = 0; ks < PLEN / 8; ks++) {
        int k0 = ks * 8;
        uint32_t ah[4], al[4];
        ah[0] = sAhi[a0 + k0];     al[0] = sAlo[a0 + k0];
        ah[1] = sAhi[a1 + k0];     al[1] = sAlo[a1 + k0];
        ah[2] = sAhi[a0 + k0 + 4]; al[2] = sAlo[a0 + k0 + 4];
        ah[3] = sAhi[a1 + k0 + 4]; al[3] = sAlo[a1 + k0 + 4];
#pragma unroll
        for (int nt = 0; nt < 4; nt++) {
            int nrow = (nh * 32 + nt * 8 + g) * PSTRIDE + t4;
            uint32_t bh0 = sWhi[nrow + k0];
            uint32_t bh1 = sWhi[nrow + k0 + 4];
            uint32_t bl0 = sWlo[nrow + k0];
            uint32_t bl1 = sWlo[nrow + k0 + 4];
            mma_tf32(acc[nt], ah, bh0, bh1);   // hi*hi
            mma_tf32(acc[nt], ah, bl0, bl1);   // hi*lo
            mma_tf32(acc[nt], al, bh0, bh1);   // lo*hi
        }
    }

    // epilogue: atomic add into bias-initialized out
#pragma unroll
    for (int nt = 0; nt < 4; nt++) {
        int pcol = pb * 64 + nh * 32 + nt * 8 + t4 * 2;
        int brow = mi * 16 + g;
        atomicAdd(&out[brow * NP + pcol],           acc[nt][0]);
        atomicAdd(&out[brow * NP + pcol + 1],       acc[nt][1]);
        atomicAdd(&out[(brow + 8) * NP + pcol],     acc[nt][2]);
        atomicAdd(&out[(brow + 8) * NP + pcol + 1], acc[nt][3]);
    }
}

// ---------------- launch ----------------
extern "C" void kernel_launch(void* const* d_in, const int* in_sizes, int n_in,
                              void* d_out, int out_size) {
    const float* atom  = (const float*)d_in[0];
    const float* pos   = (const float*)d_in[1];
    const float* clos  = (const float*)d_in[2];
    const float* Wm    = (const float*)d_in[3];
    const float* bias  = (const float*)d_in[4];
    const float* tmask = (const float*)d_in[5];
    const float* rmask = (const float*)d_in[6];
    const int*   aidx  = (const int*)d_in[7];
    const int*   rpos  = (const int*)d_in[8];
    float* out = (float*)d_out;

    cudaFuncSetAttribute(fwd_fft_kernel,
                         cudaFuncAttributeMaxDynamicSharedMemorySize, FFT_SMEM);
    cudaFuncSetAttribute(inv_fft_kernel,
                         cudaFuncAttributeMaxDynamicSharedMemorySize, FFT_SMEM);
    cudaFuncSetAttribute(proj_kernel,
                         cudaFuncAttributeMaxDynamicSharedMemorySize, PROJ_SMEM);

    fwd_fft_kernel<<<NA + NS + 2, FFTTHREADS, FFT_SMEM>>>(atom, pos, clos, bias, out);

    dim3 cg((F + 127) / 128, NB / BG, NZ);
    combine_kernel<<<cg, 128>>>(tmask, rmask, aidx, rpos);

    inv_fft_kernel<<<NB, FFTTHREADS, FFT_SMEM>>>();

    dim3 pg(NP / 64, PSPLIT);
    proj_kernel<<<pg, 256, FFT_SMEM < PROJ_SMEM ? PROJ_SMEM : PROJ_SMEM>>>(Wm, out);
}

// round 17
// speedup vs baseline: 1.3543x; 1.0257x over previous
#include <cuda_runtime.h>
#include <stdint.h>

#define D     10000
#define F     5001      // Hermitian bins 0..5000
#define NB    64
#define NS    128
#define NA    10
#define NR    8
#define NP    256
#define FFTTHREADS 1024
#define BG    8         // batches per combine block (known-good inner shape)
#define SQ    32        // tokens per combine z-slice
#define NZ    4         // combine z-slices -> 1280 blocks

// proj tiling (tensor-core, pre-split hi/lo) -- R12 known-good
#define PSPLIT 125
#define PLEN   80       // D / PSPLIT, divisible by 8
#define PSTRIDE 84      // row stride (words): 21g+t4 mod 32 hits all banks
#define PROJ_SMEM (4 * 64 * PSTRIDE * 4)   // 86016 B -> 2 CTAs/SM

// FFT skew: pad 3 float2 per decade (stage-0 store stride 13)
__device__ __forceinline__ int SKF(int i) { return i + 3 * (i / 10); }
#define SBUF  13000
#define FFT_SMEM (2 * SBUF * 8)    // 208000 B

// ---------------- device scratch ----------------
__device__ float2 Fa_g[NA * F];
__device__ float2 Fp_g[NS * F];
__device__ float2 Fc_g[F];
__device__ float2 Freq_g[NZ][NB * F];          // partial accumulators
__device__ float  Mol_g[NB * D];

__device__ __forceinline__ float2 cmulf(float2 a, float2 b) {
    return make_float2(a.x * b.x - a.y * b.y, a.x * b.y + a.y * b.x);
}

// DFT-5 constants: W5 = e^{-2pi i/5}
#define C51  0.30901699437494742f
#define S51  0.95105651629515357f
#define C52 (-0.80901699437494745f)
#define S52  0.58778525229247314f
// W10^t = (CT_t, -ST_t)
#define CT1  0.80901699437494742f
#define ST1  0.58778525229247314f
#define CT2  0.30901699437494742f
#define ST2  0.95105651629515357f

// ---------------- DFT-5 (Winograd-style, immediate constants) ----------
__device__ __forceinline__ void dft5(const float2* a, float2* A) {
    float2 t1 = make_float2(a[1].x + a[4].x, a[1].y + a[4].y);
    float2 t2 = make_float2(a[2].x + a[3].x, a[2].y + a[3].y);
    float2 t3 = make_float2(a[1].x - a[4].x, a[1].y - a[4].y);
    float2 t4 = make_float2(a[2].x - a[3].x, a[2].y - a[3].y);
    A[0] = make_float2(a[0].x + t1.x + t2.x, a[0].y + t1.y + t2.y);
    float2 b1 = make_float2(a[0].x + C51 * t1.x + C52 * t2.x,
                            a[0].y + C51 * t1.y + C52 * t2.y);
    float2 b2 = make_float2(a[0].x + C52 * t1.x + C51 * t2.x,
                            a[0].y + C52 * t1.y + C51 * t2.y);
    float2 p  = make_float2(S51 * t3.x + S52 * t4.x, S51 * t3.y + S52 * t4.y);
    float2 q  = make_float2(S52 * t3.x - S51 * t4.x, S52 * t3.y - S51 * t4.y);
    A[1] = make_float2(b1.x + p.y, b1.y - p.x);
    A[4] = make_float2(b1.x - p.y, b1.y + p.x);
    A[2] = make_float2(b2.x + q.y, b2.y - q.x);
    A[3] = make_float2(b2.x - q.y, b2.y + q.x);
}

// ---------------- DFT-10 = 2 x DFT-5 + radix-2 combine ----------------
__device__ __forceinline__ void dft10(const float2* u, float2* v) {
    float2 E[5], O[5];
    {
        float2 a[5];
#pragma unroll
        for (int r = 0; r < 5; r++) a[r] = u[2 * r];
        dft5(a, E);
#pragma unroll
        for (int r = 0; r < 5; r++) a[r] = u[2 * r + 1];
        dft5(a, O);
    }
    float2 wo;
    v[0] = make_float2(E[0].x + O[0].x, E[0].y + O[0].y);
    v[5] = make_float2(E[0].x - O[0].x, E[0].y - O[0].y);
    wo = cmulf(O[1], make_float2(CT1, -ST1));
    v[1] = make_float2(E[1].x + wo.x, E[1].y + wo.y);
    v[6] = make_float2(E[1].x - wo.x, E[1].y - wo.y);
    wo = cmulf(O[2], make_float2(CT2, -ST2));
    v[2] = make_float2(E[2].x + wo.x, E[2].y + wo.y);
    v[7] = make_float2(E[2].x - wo.x, E[2].y - wo.y);
    wo = cmulf(O[3], make_float2(-CT2, -ST2));
    v[3] = make_float2(E[3].x + wo.x, E[3].y + wo.y);
    v[8] = make_float2(E[3].x - wo.x, E[3].y - wo.y);
    wo = cmulf(O[4], make_float2(-CT1, -ST1));
    v[4] = make_float2(E[4].x + wo.x, E[4].y + wo.y);
    v[9] = make_float2(E[4].x - wo.x, E[4].y - wo.y);
}

// ---------------- on-the-fly stage twiddles: W^(row*t), t=1..9 ----------
__device__ __forceinline__ void twiddle9_otf(float2* v, int row) {
    float s, c;
    sincospif((float)row * (-1.0f / 5000.0f), &s, &c);
    float2 w1 = make_float2(c, s);
    float2 w2 = cmulf(w1, w1);
    float2 w3 = cmulf(w2, w1);
    float2 w4 = cmulf(w2, w2);
    float2 w5 = cmulf(w4, w1);
    float2 w6 = cmulf(w4, w2);
    float2 w7 = cmulf(w4, w3);
    float2 w8 = cmulf(w4, w4);
    float2 w9 = cmulf(w8, w1);
    v[1] = cmulf(v[1], w1);
    v[2] = cmulf(v[2], w2);
    v[3] = cmulf(v[3], w3);
    v[4] = cmulf(v[4], w4);
    v[5] = cmulf(v[5], w5);
    v[6] = cmulf(v[6], w6);
    v[7] = cmulf(v[7], w7);
    v[8] = cmulf(v[8], w8);
    v[9] = cmulf(v[9], w9);
}

// ---------------- middle stages 1 & 2 (smem -> smem) ----------------
__device__ __forceinline__ void fft_mid(float2* bufA, float2* bufB, int bf) {
    if (bf < 1000) {
        int j = bf / 10, k = bf - j * 10;
        float2 u[10];
#pragma unroll
        for (int q = 0; q < 10; q++) u[q] = bufA[SKF(bf + q * 1000)];
        float2 v[10];
        dft10(u, v);
        if (j) twiddle9_otf(v, j * 10);
        int ob = k + 100 * j;
#pragma unroll
        for (int t = 0; t < 10; t++) bufB[SKF(ob + 10 * t)] = v[t];
    }
    __syncthreads();
    if (bf < 1000) {
        int j = bf / 100, k = bf - j * 100;
        float2 u[10];
#pragma unroll
        for (int q = 0; q < 10; q++) u[q] = bufB[SKF(bf + q * 1000)];
        float2 v[10];
        dft10(u, v);
        if (j) twiddle9_otf(v, j * 100);
        int ob = k + 1000 * j;
#pragma unroll
        for (int t = 0; t < 10; t++) bufA[SKF(ob + 100 * t)] = v[t];
    }
    __syncthreads();
}

// ---------------- forward FFT (+ bias-init in extra block) -------------
__global__ void __launch_bounds__(FFTTHREADS, 1)
fwd_fft_kernel(const float* __restrict__ atom,
               const float* __restrict__ pos,
               const float* __restrict__ clos,
               const float* __restrict__ bias,
               float* __restrict__ out) {
    int vb = blockIdx.x;
    if (vb == NA + NS + 1) {   // init out = bias (must precede proj atomics)
        for (int i = threadIdx.x; i < NB * NP; i += blockDim.x)
            out[i] = bias[i & (NP - 1)];
        return;
    }
    extern __shared__ float2 sb[];
    float2* bufA = sb;
    float2* bufB = sb + SBUF;
    const float* x;
    float2* outF;
    if (vb < NA)           { x = atom + vb * D;        outF = Fa_g + vb * F; }
    else if (vb < NA + NS) { x = pos + (vb - NA) * D;  outF = Fp_g + (vb - NA) * F; }
    else                   { x = clos;                 outF = Fc_g; }

    int bf = threadIdx.x;
    if (bf < 1000) {
        float2 u[10];
#pragma unroll
        for (int q = 0; q < 10; q++) u[q] = make_float2(x[bf + q * 1000], 0.f);
        float2 v[10];
        dft10(u, v);
        if (bf) twiddle9_otf(v, bf);
#pragma unroll
        for (int t = 0; t < 10; t++) bufA[13 * bf + t] = v[t];
    }
    __syncthreads();

    fft_mid(bufA, bufB, bf);

    if (bf < 1000) {
        float2 u[10];
#pragma unroll
        for (int q = 0; q < 10; q++) u[q] = bufA[SKF(bf + q * 1000)];
        float2 v[10];
        dft10(u, v);
#pragma unroll
        for (int t = 0; t < 10; t++) {
            int p = bf + 1000 * t;
            if (p < F) outF[p] = v[t];
        }
    }
}

// ---------------- frequency combine: 4-way z-split, BG=8 ---------------
// z in [0,4): tokens s in [32z, 32z+32). Rings ride in z==3.
__global__ void combine_kernel(const float* __restrict__ tmask,
                               const float* __restrict__ rmask,
                               const int*   __restrict__ aidx,
                               const int*   __restrict__ rpos) {
    __shared__ float2 s_mi[BG][SQ];
    __shared__ int   s_rp[BG][NR][2];
    __shared__ float s_rm[BG][NR];
    __shared__ float2 s_fa[NA][128];

    int b0 = blockIdx.y * BG;
    int z  = blockIdx.z;
    int s0 = z * SQ;
    int tx = threadIdx.x;

    for (int t = tx; t < BG * SQ; t += 128) {
        int bb = t / SQ, s = t % SQ;
        s_mi[bb][s] = make_float2(tmask[(b0 + bb) * NS + s0 + s],
                                  __int_as_float(aidx[(b0 + bb) * NS + s0 + s]));
    }
    if (z == NZ - 1) {
        for (int t = tx; t < BG * NR; t += 128) {
            int bb = t / NR, r = t % NR;
            s_rp[bb][r][0] = rpos[((b0 + bb) * NR + r) * 2 + 0];
            s_rp[bb][r][1] = rpos[((b0 + bb) * NR + r) * 2 + 1];
            s_rm[bb][r]    = rmask[(b0 + bb) * NR + r];
        }
    }
    int f = blockIdx.x * 128 + tx;
    if (f < F) {
        for (int i = 0; i < NA; i++) s_fa[i][tx] = Fa_g[i * F + f];
    }
    __syncthreads();
    if (f >= F) return;

    float2 acc[BG];
#pragma unroll
    for (int bb = 0; bb < BG; bb++) acc[bb] = make_float2(0.f, 0.f);

#pragma unroll 4
    for (int s = 0; s < SQ; s++) {
        float2 fp = Fp_g[(s0 + s) * F + f];
        float nfpy = -fp.y;
#pragma unroll
        for (int bb = 0; bb < BG; bb++) {
            float2 mi = s_mi[bb][s];
            int    a  = __float_as_int(mi.y);
            float2 fa = s_fa[a][tx];
            float p = mi.x * fa.x;
            float q = mi.x * fa.y;
            acc[bb].x += p * fp.x;
            acc[bb].x += q * nfpy;
            acc[bb].y += p * fp.y;
            acc[bb].y += q * fp.x;
        }
    }
    if (z == NZ - 1) {
        float2 fc = Fc_g[f];
#pragma unroll
        for (int bb = 0; bb < BG; bb++) {
            for (int r = 0; r < NR; r++) {
                float2 f0 = Fp_g[s_rp[bb][r][0] * F + f];
                float2 f1 = Fp_g[s_rp[bb][r][1] * F + f];
                float2 t  = cmulf(cmulf(f0, f1), fc);
                float mm  = s_rm[bb][r];
                acc[bb].x += mm * t.x;
                acc[bb].y += mm * t.y;
            }
        }
    }
#pragma unroll
    for (int bb = 0; bb < BG; bb++)
        Freq_g[z][(b0 + bb) * F + f] = acc[bb];
}

// ---------------- inverse FFT (sum 4 partials, Hermitian, conj) --------
__global__ void __launch_bounds__(FFTTHREADS, 1)
inv_fft_kernel() {
    extern __shared__ float2 sb[];
    float2* bufA = sb;
    float2* bufB = sb + SBUF;
    int b = blockIdx.x;
    const float2* in0 = Freq_g[0] + b * F;
    const float2* in1 = Freq_g[1] + b * F;
    const float2* in2 = Freq_g[2] + b * F;
    const float2* in3 = Freq_g[3] + b * F;

    int bf = threadIdx.x;
    if (bf < 1000) {
        float2 u[10];
#pragma unroll
        for (int q = 0; q < 10; q++) {
            int i = bf + q * 1000;
            int ii = (i < F) ? i : (D - i);
            float2 z0 = in0[ii], z1 = in1[ii], z2 = in2[ii], z3 = in3[ii];
            float2 z = make_float2((z0.x + z1.x) + (z2.x + z3.x),
                                   (z0.y + z1.y) + (z2.y + z3.y));
            if (i < F) z.y = -z.y;     // conj for lower half
            u[q] = z;
        }
        float2 v[10];
        dft10(u, v);
        if (bf) twiddle9_otf(v, bf);
#pragma unroll
        for (int t = 0; t < 10; t++) bufA[13 * bf + t] = v[t];
    }
    __syncthreads();

    fft_mid(bufA, bufB, bf);

    if (bf < 1000) {
        float2 u[10];
#pragma unroll
        for (int q = 0; q < 10; q++) u[q] = bufA[SKF(bf + q * 1000)];
        float2 v[10];
        dft10(u, v);
        const float inv = 1.0f / (float)D;
        float* mo = Mol_g + b * D;
#pragma unroll
        for (int t = 0; t < 10; t++) mo[bf + 1000 * t] = v[t].x * inv;
    }
}

// ---------------- 3xTF32 helpers ----------------
__device__ __forceinline__ void tf32_split(float x, uint32_t& hi, uint32_t& lo) {
    asm("cvt.rna.tf32.f32 %0, %1;" : "=r"(hi) : "f"(x));
    float r = x - __uint_as_float(hi);
    asm("cvt.rna.tf32.f32 %0, %1;" : "=r"(lo) : "f"(r));
}

__device__ __forceinline__ void mma_tf32(float* c, const uint32_t* a,
                                         uint32_t b0, uint32_t b1) {
    asm volatile(
        "mma.sync.aligned.m16n8k8.row.col.f32.tf32.tf32.f32 "
        "{%0,%1,%2,%3}, {%4,%5,%6,%7}, {%8,%9}, {%0,%1,%2,%3};"
        : "+f"(c[0]), "+f"(c[1]), "+f"(c[2]), "+f"(c[3])
        : "r"(a[0]), "r"(a[1]), "r"(a[2]), "r"(a[3]), "r"(b0), "r"(b1));
}

// ---------------- projection: 3xTF32, pre-split tiles, split-k ---------
// R12 known-good. grid (NP/64 = 4, PSPLIT = 125), block 256, 2 CTAs/SM.
__global__ void __launch_bounds__(256)
proj_kernel(const float* __restrict__ Wm, float* __restrict__ out) {
    extern __shared__ uint32_t ps[];
    uint32_t* sAhi = ps;                          // [64][PSTRIDE]
    uint32_t* sAlo = ps + 64 * PSTRIDE;
    uint32_t* sWhi = ps + 2 * 64 * PSTRIDE;
    uint32_t* sWlo = ps + 3 * 64 * PSTRIDE;
    int pb = blockIdx.x;
    int ds = blockIdx.y;
    int dbase = ds * PLEN;
    int tid = threadIdx.x;

    // load + split once: 5 float4 per thread per tile
#pragma unroll
    for (int j = 0; j < 5; j++) {
        int v = tid + j * 256;                 // v < 1280
        int r = v / 20, cq = v - r * 20;
        float4 x = *reinterpret_cast<const float4*>(&Mol_g[r * D + dbase + cq * 4]);
        uint4 h, l;
        tf32_split(x.x, h.x, l.x);
        tf32_split(x.y, h.y, l.y);
        tf32_split(x.z, h.z, l.z);
        tf32_split(x.w, h.w, l.w);
        *reinterpret_cast<uint4*>(&sAhi[r * PSTRIDE + cq * 4]) = h;
        *reinterpret_cast<uint4*>(&sAlo[r * PSTRIDE + cq * 4]) = l;
    }
#pragma unroll
    for (int j = 0; j < 5; j++) {
        int v = tid + j * 256;
        int r = v / 20, cq = v - r * 20;
        float4 x = *reinterpret_cast<const float4*>(&Wm[(pb * 64 + r) * D + dbase + cq * 4]);
        uint4 h, l;
        tf32_split(x.x, h.x, l.x);
        tf32_split(x.y, h.y, l.y);
        tf32_split(x.z, h.z, l.z);
        tf32_split(x.w, h.w, l.w);
        *reinterpret_cast<uint4*>(&sWhi[r * PSTRIDE + cq * 4]) = h;
        *reinterpret_cast<uint4*>(&sWlo[r * PSTRIDE + cq * 4]) = l;
    }
    __syncthreads();

    int wid  = tid >> 5;
    int lane = tid & 31;
    int g  = lane >> 2;        // group id 0..7
    int t4 = lane & 3;         // thread-in-group 0..3
    int mi = wid & 3;          // m-tile (16 b rows)
    int nh = wid >> 2;         // n-half (32 p cols)

    int arow = mi * 16 + g;
    int a0 = arow * PSTRIDE + t4;
    int a1 = (arow + 8) * PSTRIDE + t4;
    float acc[4][4];
#pragma unroll
    for (int i = 0; i < 4; i++)
#pragma unroll
        for (int j = 0; j < 4; j++) acc[i][j] = 0.f;

#pragma unroll
    for (int ks = 0; ks < PLEN / 8; ks++) {
        int k0 = ks * 8;
        uint32_t ah[4], al[4];
        ah[0] = sAhi[a0 + k0];     al[0] = sAlo[a0 + k0];
        ah[1] = sAhi[a1 + k0];     al[1] = sAlo[a1 + k0];
        ah[2] = sAhi[a0 + k0 + 4]; al[2] = sAlo[a0 + k0 + 4];
        ah[3] = sAhi[a1 + k0 + 4]; al[3] = sAlo[a1 + k0 + 4];
#pragma unroll
        for (int nt = 0; nt < 4; nt++) {
            int nrow = (nh * 32 + nt * 8 + g) * PSTRIDE + t4;
            uint32_t bh0 = sWhi[nrow + k0];
            uint32_t bh1 = sWhi[nrow + k0 + 4];
            uint32_t bl0 = sWlo[nrow + k0];
            uint32_t bl1 = sWlo[nrow + k0 + 4];
            mma_tf32(acc[nt], ah, bh0, bh1);   // hi*hi
            mma_tf32(acc[nt], ah, bl0, bl1);   // hi*lo
            mma_tf32(acc[nt], al, bh0, bh1);   // lo*hi
        }
    }

    // epilogue: atomic add into bias-initialized out
#pragma unroll
    for (int nt = 0; nt < 4; nt++) {
        int pcol = pb * 64 + nh * 32 + nt * 8 + t4 * 2;
        int brow = mi * 16 + g;
        atomicAdd(&out[brow * NP + pcol],           acc[nt][0]);
        atomicAdd(&out[brow * NP + pcol + 1],       acc[nt][1]);
        atomicAdd(&out[(brow + 8) * NP + pcol],     acc[nt][2]);
        atomicAdd(&out[(brow + 8) * NP + pcol + 1], acc[nt][3]);
    }
}

// ---------------- launch ----------------
extern "C" void kernel_launch(void* const* d_in, const int* in_sizes, int n_in,
                              void* d_out, int out_size) {
    const float* atom  = (const float*)d_in[0];
    const float* pos   = (const float*)d_in[1];
    const float* clos  = (const float*)d_in[2];
    const float* Wm    = (const float*)d_in[3];
    const float* bias  = (const float*)d_in[4];
    const float* tmask = (const float*)d_in[5];
    const float* rmask = (const float*)d_in[6];
    const int*   aidx  = (const int*)d_in[7];
    const int*   rpos  = (const int*)d_in[8];
    float* out = (float*)d_out;

    cudaFuncSetAttribute(fwd_fft_kernel,
                         cudaFuncAttributeMaxDynamicSharedMemorySize, FFT_SMEM);
    cudaFuncSetAttribute(inv_fft_kernel,
                         cudaFuncAttributeMaxDynamicSharedMemorySize, FFT_SMEM);
    cudaFuncSetAttribute(proj_kernel,
                         cudaFuncAttributeMaxDynamicSharedMemorySize, PROJ_SMEM);

    fwd_fft_kernel<<<NA + NS + 2, FFTTHREADS, FFT_SMEM>>>(atom, pos, clos, bias, out);

    dim3 cg((F + 127) / 128, NB / BG, NZ);
    combine_kernel<<<cg, 128>>>(tmask, rmask, aidx, rpos);

    inv_fft_kernel<<<NB, FFTTHREADS, FFT_SMEM>>>();

    dim3 pg(NP / 64, PSPLIT);
    proj_kernel<<<pg, 256, PROJ_SMEM>>>(Wm, out);
}